// round 1
// baseline (speedup 1.0000x reference)
#include <cuda_runtime.h>
#include <cstdint>

#define BATCH 64
#define EMB   128
#define NB    64
#define RANK  4
#define SEQ   4096

// sqrt(log2(e)) — folds the natural-exp into a single ex2.approx
#define SQRT_LOG2E 1.2011224087864498f

// ---------------------------------------------------------------------------
// Scratch (device globals; no allocation allowed)
// ---------------------------------------------------------------------------
__device__ float g_h1[BATCH * 512];            // relu(f@W1+b1)
__device__ float g_h2[BATCH * 1024];           // relu(h1@W2+b2)
// omega packed as (even, odd) float pairs: index [((b*NB+n)*RANK+r)*2 + side]
__device__ float g_om[BATCH * NB * RANK * 2];

// ---------------------------------------------------------------------------
// Small-M GEMM: out[i][j] = (relu?)(sum_k A[i,k] * W[k,j] + bias[j])
// block(32,4): 32 x-threads each own 4 consecutive columns, 4 y-threads = rows
// grid(N/128, BATCH/4)
// SRC: 0 = Ain param, 1 = g_h1, 2 = g_h2
// DST: 0 = g_h1, 1 = g_h2, 2 = packed omega (g_om)
// ---------------------------------------------------------------------------
template <int K, int N, bool RELU, int SRC, int DST>
__global__ __launch_bounds__(128)
void gemm_kernel(const float* __restrict__ Ain,
                 const float* __restrict__ W,
                 const float* __restrict__ bias)
{
    const float* A = (SRC == 0) ? Ain : (SRC == 1 ? g_h1 : g_h2);

    const int tx = threadIdx.x;               // 0..31
    const int ty = threadIdx.y;               // 0..3
    const int j  = (blockIdx.x * 32 + tx) * 4;
    const int i  = blockIdx.y * 4 + ty;

    const float* Arow = A + i * K;

    float a0 = 0.f, a1 = 0.f, a2 = 0.f, a3 = 0.f;

    #pragma unroll 4
    for (int k = 0; k < K; k += 4) {
        const float4 av = *reinterpret_cast<const float4*>(Arow + k);
        float aa[4] = {av.x, av.y, av.z, av.w};
        #pragma unroll
        for (int kk = 0; kk < 4; kk++) {
            const float4 wv = *reinterpret_cast<const float4*>(W + (k + kk) * N + j);
            a0 = fmaf(aa[kk], wv.x, a0);
            a1 = fmaf(aa[kk], wv.y, a1);
            a2 = fmaf(aa[kk], wv.z, a2);
            a3 = fmaf(aa[kk], wv.w, a3);
        }
    }

    const float4 bv = *reinterpret_cast<const float4*>(bias + j);
    a0 += bv.x; a1 += bv.y; a2 += bv.z; a3 += bv.w;

    if (RELU) {
        a0 = fmaxf(a0, 0.f); a1 = fmaxf(a1, 0.f);
        a2 = fmaxf(a2, 0.f); a3 = fmaxf(a3, 0.f);
    }

    if (DST == 0) {
        *reinterpret_cast<float4*>(g_h1 + i * N + j) = make_float4(a0, a1, a2, a3);
    } else if (DST == 1) {
        *reinterpret_cast<float4*>(g_h2 + i * N + j) = make_float4(a0, a1, a2, a3);
    } else {
        // coeff[b][j], j in [0,512). Rows 0..63 of omega (j<256) are the "even"
        // half, rows 64..127 (j>=256) the "odd" half. Pack as (even,odd) pairs.
        const int side = (j >= 256) ? 1 : 0;
        const int jj   = j - side * 256;      // 4-aligned
        const int n    = jj >> 2;             // basis index, r = 0..3 across accs
        float* dst = g_om + ((i * NB + n) * RANK) * 2 + side;
        dst[0] = a0; dst[2] = a1; dst[4] = a2; dst[6] = a3;
    }
}

// ---------------------------------------------------------------------------
// Basis + rank-4 projection kernel.
// grid(SEQ/1024, BATCH), block 256; each thread handles 4 time points.
// Per (point, n): 1 ex2.approx + 1 cos.approx + 4 scalar FMAs + 4 fma.rn.f32x2
// (accumulating the (even,odd) pair for each of 4 ranks).
// ---------------------------------------------------------------------------
__global__ __launch_bounds__(256)
void basis_kernel(const float* __restrict__ t,
                  const float* __restrict__ mu,
                  const float* __restrict__ alpha,
                  const float* __restrict__ beta,
                  const float* __restrict__ gamma,
                  float* __restrict__ out)
{
    __shared__ __align__(16) float4 s_bp[NB];          // (a2, -a2*mu, beta, gamma)
    __shared__ __align__(16) float2 s_om[NB * RANK];   // (even, odd) pairs

    const int tid = threadIdx.x;
    const int b   = blockIdx.y;

    if (tid < NB) {
        const float a2 = alpha[tid] * SQRT_LOG2E;
        s_bp[tid] = make_float4(a2, -a2 * mu[tid], beta[tid], gamma[tid]);
    }
    {
        const float2* src = reinterpret_cast<const float2*>(g_om) + b * (NB * RANK);
        s_om[tid] = src[tid];    // 256 threads copy 256 float2
    }
    __syncthreads();

    const int s0 = blockIdx.x * 1024 + tid;
    const float* trow = t + (size_t)b * SEQ;

    float tv[4];
    #pragma unroll
    for (int p = 0; p < 4; p++) tv[p] = trow[s0 + 256 * p];

    unsigned long long acc[RANK][4];
    #pragma unroll
    for (int r = 0; r < RANK; r++)
        #pragma unroll
        for (int p = 0; p < 4; p++) acc[r][p] = 0ull;

    const unsigned long long* omq =
        reinterpret_cast<const unsigned long long*>(s_om);

    #pragma unroll 2
    for (int n = 0; n < NB; n++) {
        const float4 bp = s_bp[n];
        const ulonglong2 q0 = *reinterpret_cast<const ulonglong2*>(omq + n * 4);
        const ulonglong2 q1 = *reinterpret_cast<const ulonglong2*>(omq + n * 4 + 2);
        const unsigned long long O[4] = {q0.x, q0.y, q1.x, q1.y};

        #pragma unroll
        for (int p = 0; p < 4; p++) {
            const float u  = fmaf(bp.x, tv[p], bp.y);   // a2*(t - mu)
            const float nv = -u * u;
            float e;
            asm("ex2.approx.f32 %0, %1;" : "=f"(e) : "f"(nv));
            const float w = fmaf(bp.z, tv[p], bp.w);    // beta*t + gamma
            float c;
            asm("cos.approx.f32 %0, %1;" : "=f"(c) : "f"(w));
            const float pr = e * c;                      // h_t[b,s,n]
            unsigned long long pp;
            asm("mov.b64 %0, {%1, %1};" : "=l"(pp) : "f"(pr));
            #pragma unroll
            for (int r = 0; r < RANK; r++)
                asm("fma.rn.f32x2 %0, %1, %2, %0;"
                    : "+l"(acc[r][p]) : "l"(pp), "l"(O[r]));
        }
    }

    float* obase = out + (size_t)b * (2 * SEQ * RANK);
    #pragma unroll
    for (int p = 0; p < 4; p++) {
        const int s = s0 + 256 * p;
        float ev[4], od[4];
        #pragma unroll
        for (int r = 0; r < RANK; r++)
            asm("mov.b64 {%0, %1}, %2;" : "=f"(ev[r]), "=f"(od[r]) : "l"(acc[r][p]));
        float4* op = reinterpret_cast<float4*>(obase + (size_t)s * 8);
        op[0] = make_float4(ev[0], ev[1], ev[2], ev[3]);   // even row 2s
        op[1] = make_float4(od[0], od[1], od[2], od[3]);   // odd  row 2s+1
    }
}

// ---------------------------------------------------------------------------
// Launch
// ---------------------------------------------------------------------------
extern "C" void kernel_launch(void* const* d_in, const int* in_sizes, int n_in,
                              void* d_out, int out_size)
{
    const float* f     = (const float*)d_in[0];
    const float* t     = (const float*)d_in[1];
    const float* W1    = (const float*)d_in[2];
    const float* b1    = (const float*)d_in[3];
    const float* W2    = (const float*)d_in[4];
    const float* b2    = (const float*)d_in[5];
    const float* W3    = (const float*)d_in[6];
    const float* b3    = (const float*)d_in[7];
    const float* mu    = (const float*)d_in[8];
    const float* alpha = (const float*)d_in[9];
    const float* beta  = (const float*)d_in[10];
    const float* gamma = (const float*)d_in[11];
    float* out = (float*)d_out;

    const dim3 blk(32, 4);
    // h1 = relu(f @ W1 + b1)          [64, 512]
    gemm_kernel<128, 512, true, 0, 0><<<dim3(4, 16), blk>>>(f, W1, b1);
    // h2 = relu(h1 @ W2 + b2)         [64, 1024]
    gemm_kernel<512, 1024, true, 1, 1><<<dim3(8, 16), blk>>>(nullptr, W2, b2);
    // coeff = h2 @ W3 + b3 -> packed omega
    gemm_kernel<1024, 512, false, 2, 2><<<dim3(4, 16), blk>>>(nullptr, W3, b3);
    // basis + projection
    basis_kernel<<<dim3(SEQ / 1024, BATCH), 256>>>(t, mu, alpha, beta, gamma, out);
}

// round 2
// speedup vs baseline: 1.7525x; 1.7525x over previous
#include <cuda_runtime.h>
#include <cstdint>

#define BATCH 64
#define EMB   128
#define NB    64
#define RANK  4
#define SEQ   4096

// sqrt(log2(e)) — folds natural-exp into a single ex2.approx
#define SQRT_LOG2E 1.2011224087864498f

#define KS2 2   // split-K factor for layer 2
#define KS3 4   // split-K factor for layer 3
#define OM_SZ (BATCH * NB * RANK * 2)

// ---------------------------------------------------------------------------
// Scratch (device globals; no allocation allowed)
// ---------------------------------------------------------------------------
__device__ float g_h1[BATCH * 512];                // relu(f@W1+b1)
__device__ float g_h2[KS2 * BATCH * 1024];         // pre-relu partials of layer 2
__device__ float g_om[KS3 * OM_SZ];                // packed omega partials
// omega packing within one partial: [((b*NB+n)*RANK+r)*2 + side]

// ---------------------------------------------------------------------------
// GEMM: tile = 8 rows x 128 cols, 256 threads (32,8), each thread 1 row x 4
// cols via float4 W loads. Optional split-K via blockIdx.z -> disjoint
// partial buffers (bias added only in split 0; nonlinearity deferred to the
// consumer, which sums partials).
// SRC: 0 = Ain param, 1 = g_h1, 2 = relu(sum of g_h2 partials)
// DST: 0 = g_h1 (with relu), 1 = g_h2 partial, 2 = packed omega partial
// ---------------------------------------------------------------------------
template <int K, int KH, int N, int SRC, int DST>
__global__ __launch_bounds__(256)
void gemm_kernel(const float* __restrict__ Ain,
                 const float* __restrict__ W,
                 const float* __restrict__ bias)
{
    const int tx = threadIdx.x;                 // 0..31
    const int ty = threadIdx.y;                 // 0..7
    const int j  = blockIdx.x * 128 + tx * 4;   // column
    const int i  = blockIdx.y * 8 + ty;         // row
    const int kz = blockIdx.z;
    const int k0 = kz * KH;

    float a0, a1, a2, a3;
    if (kz == 0) {
        const float4 bv = *reinterpret_cast<const float4*>(bias + j);
        a0 = bv.x; a1 = bv.y; a2 = bv.z; a3 = bv.w;
    } else {
        a0 = a1 = a2 = a3 = 0.f;
    }

    #pragma unroll 4
    for (int k = k0; k < k0 + KH; k += 4) {
        float4 av;
        if (SRC == 0) {
            av = *reinterpret_cast<const float4*>(Ain + i * K + k);
        } else if (SRC == 1) {
            av = *reinterpret_cast<const float4*>(g_h1 + i * K + k);
        } else {
            const float4 p0 = *reinterpret_cast<const float4*>(g_h2 + i * K + k);
            const float4 p1 = *reinterpret_cast<const float4*>(g_h2 + BATCH * 1024 + i * K + k);
            av.x = fmaxf(p0.x + p1.x, 0.f);
            av.y = fmaxf(p0.y + p1.y, 0.f);
            av.z = fmaxf(p0.z + p1.z, 0.f);
            av.w = fmaxf(p0.w + p1.w, 0.f);
        }
        const float aa[4] = {av.x, av.y, av.z, av.w};
        #pragma unroll
        for (int kk = 0; kk < 4; kk++) {
            const float4 wv = *reinterpret_cast<const float4*>(W + (k + kk) * N + j);
            a0 = fmaf(aa[kk], wv.x, a0);
            a1 = fmaf(aa[kk], wv.y, a1);
            a2 = fmaf(aa[kk], wv.z, a2);
            a3 = fmaf(aa[kk], wv.w, a3);
        }
    }

    if (DST == 0) {
        a0 = fmaxf(a0, 0.f); a1 = fmaxf(a1, 0.f);
        a2 = fmaxf(a2, 0.f); a3 = fmaxf(a3, 0.f);
        *reinterpret_cast<float4*>(g_h1 + i * N + j) = make_float4(a0, a1, a2, a3);
    } else if (DST == 1) {
        *reinterpret_cast<float4*>(g_h2 + kz * (BATCH * 1024) + i * N + j) =
            make_float4(a0, a1, a2, a3);
    } else {
        // coeff[b][j], j in [0,512). j<256 -> "even" half, j>=256 -> "odd".
        const int side = (j >= 256) ? 1 : 0;
        const int jj   = j - side * 256;       // 4-aligned
        const int n    = jj >> 2;              // basis index; r = 0..3 across accs
        float* dst = g_om + kz * OM_SZ + ((i * NB + n) * RANK) * 2 + side;
        dst[0] = a0; dst[2] = a1; dst[4] = a2; dst[6] = a3;
    }
}

// ---------------------------------------------------------------------------
// Basis + rank-4 projection. grid(SEQ/512, BATCH), block 256, 2 points/thread.
// Per (point, n): 1 ex2.approx + 1 cos.approx + ~4 scalar FMAs + 4 fma.rn.f32x2
// accumulating the (even,odd) pair per rank. Sums the KS3 omega partials on
// the shared-memory load.
// ---------------------------------------------------------------------------
__global__ __launch_bounds__(256)
void basis_kernel(const float* __restrict__ t,
                  const float* __restrict__ mu,
                  const float* __restrict__ alpha,
                  const float* __restrict__ beta,
                  const float* __restrict__ gamma,
                  float* __restrict__ out)
{
    __shared__ __align__(16) float4 s_bp[NB];          // (a2, -a2*mu, beta, gamma)
    __shared__ __align__(16) float2 s_om[NB * RANK];   // (even, odd) pairs

    const int tid = threadIdx.x;
    const int b   = blockIdx.y;

    if (tid < NB) {
        const float a2 = alpha[tid] * SQRT_LOG2E;
        s_bp[tid] = make_float4(a2, -a2 * mu[tid], beta[tid], gamma[tid]);
    }
    {
        const float2* src = reinterpret_cast<const float2*>(g_om) + b * (NB * RANK);
        float2 acc = src[tid];
        #pragma unroll
        for (int z = 1; z < KS3; z++) {
            const float2 p = src[z * (OM_SZ / 2) + tid];
            acc.x += p.x; acc.y += p.y;
        }
        s_om[tid] = acc;
    }
    __syncthreads();

    const int s0 = blockIdx.x * 512 + tid;
    const float* trow = t + (size_t)b * SEQ;

    float tv[2];
    tv[0] = trow[s0];
    tv[1] = trow[s0 + 256];

    unsigned long long acc[RANK][2];
    #pragma unroll
    for (int r = 0; r < RANK; r++) { acc[r][0] = 0ull; acc[r][1] = 0ull; }

    const unsigned long long* omq =
        reinterpret_cast<const unsigned long long*>(s_om);

    #pragma unroll 4
    for (int n = 0; n < NB; n++) {
        const float4 bp = s_bp[n];
        const ulonglong2 q0 = *reinterpret_cast<const ulonglong2*>(omq + n * 4);
        const ulonglong2 q1 = *reinterpret_cast<const ulonglong2*>(omq + n * 4 + 2);
        const unsigned long long O[4] = {q0.x, q0.y, q1.x, q1.y};

        #pragma unroll
        for (int p = 0; p < 2; p++) {
            const float u  = fmaf(bp.x, tv[p], bp.y);   // a2*(t - mu)
            const float nv = -u * u;
            float e;
            asm("ex2.approx.f32 %0, %1;" : "=f"(e) : "f"(nv));
            const float w = fmaf(bp.z, tv[p], bp.w);    // beta*t + gamma
            float c;
            asm("cos.approx.f32 %0, %1;" : "=f"(c) : "f"(w));
            const float pr = e * c;                      // h_t[b,s,n]
            unsigned long long pp;
            asm("mov.b64 %0, {%1, %1};" : "=l"(pp) : "f"(pr));
            #pragma unroll
            for (int r = 0; r < RANK; r++)
                asm("fma.rn.f32x2 %0, %1, %2, %0;"
                    : "+l"(acc[r][p]) : "l"(pp), "l"(O[r]));
        }
    }

    float* obase = out + (size_t)b * (2 * SEQ * RANK);
    #pragma unroll
    for (int p = 0; p < 2; p++) {
        const int s = s0 + 256 * p;
        float ev[4], od[4];
        #pragma unroll
        for (int r = 0; r < RANK; r++)
            asm("mov.b64 {%0, %1}, %2;" : "=f"(ev[r]), "=f"(od[r]) : "l"(acc[r][p]));
        float4* op = reinterpret_cast<float4*>(obase + (size_t)s * 8);
        op[0] = make_float4(ev[0], ev[1], ev[2], ev[3]);   // even row 2s
        op[1] = make_float4(od[0], od[1], od[2], od[3]);   // odd  row 2s+1
    }
}

// ---------------------------------------------------------------------------
// Launch
// ---------------------------------------------------------------------------
extern "C" void kernel_launch(void* const* d_in, const int* in_sizes, int n_in,
                              void* d_out, int out_size)
{
    const float* f     = (const float*)d_in[0];
    const float* t     = (const float*)d_in[1];
    const float* W1    = (const float*)d_in[2];
    const float* b1    = (const float*)d_in[3];
    const float* W2    = (const float*)d_in[4];
    const float* b2    = (const float*)d_in[5];
    const float* W3    = (const float*)d_in[6];
    const float* b3    = (const float*)d_in[7];
    const float* mu    = (const float*)d_in[8];
    const float* alpha = (const float*)d_in[9];
    const float* beta  = (const float*)d_in[10];
    const float* gamma = (const float*)d_in[11];
    float* out = (float*)d_out;

    const dim3 blk(32, 8);
    // h1 = relu(f @ W1 + b1)                       [64, 512]
    gemm_kernel<128, 128, 512, 0, 0><<<dim3(4, 8, 1), blk>>>(f, W1, b1);
    // h2 partials = h1 @ W2 (+b2 in split 0)       [2][64, 1024]
    gemm_kernel<512, 512 / KS2, 1024, 1, 1><<<dim3(8, 8, KS2), blk>>>(nullptr, W2, b2);
    // omega partials = relu(sum h2) @ W3 (+b3)     [4][64, 512] packed
    gemm_kernel<1024, 1024 / KS3, 512, 2, 2><<<dim3(4, 8, KS3), blk>>>(nullptr, W3, b3);
    // basis + projection
    basis_kernel<<<dim3(SEQ / 512, BATCH), 256>>>(t, mu, alpha, beta, gamma, out);
}

// round 3
// speedup vs baseline: 2.3486x; 1.3401x over previous
#include <cuda_runtime.h>
#include <cstdint>

#define BATCH 64
#define EMB   128
#define NB    64
#define RANK  4
#define SEQ   4096

// sqrt(log2(e)) — folds natural-exp into a single ex2.approx
#define SQRT_LOG2E 1.2011224087864498f

#define KS1 2   // split-K, layer 1
#define KS2 4   // split-K, layer 2
#define KS3 8   // split-K, layer 3
#define OMP_STRIDE (BATCH * NB * RANK * 2)   // floats per omega partial (32768)

// ---------------------------------------------------------------------------
// Scratch (device globals; no allocation allowed)
// ---------------------------------------------------------------------------
__device__ float g_h1p[KS1 * BATCH * 512];     // pre-relu partials of layer 1
__device__ float g_h2p[KS2 * BATCH * 1024];    // pre-relu partials of layer 2
__device__ float g_om [KS3 * OMP_STRIDE];      // packed omega partials
// omega packing within one partial: [((b*NB+n)*RANK+r)*2 + side]

// ---------------------------------------------------------------------------
// GEMM: tile 8 rows x 128 cols, block(32,8); thread = 1 row x 4 cols via
// float4 W loads (coalesced 512B/warp). Split-K via blockIdx.z writes to
// disjoint partial buffers (bias only in split 0). Consumers sum the
// producer's partials inline (+relu) when loading A.
// SRCBUF: 0 = Ain param (no relu), 1 = g_h1p, 2 = g_h2p (sum NPART + relu)
// DST:    0 = g_h1p partial, 1 = g_h2p partial, 2 = packed omega partial
// ---------------------------------------------------------------------------
template <int K, int KH, int N, int SRCBUF, int NPART, int DST>
__global__ __launch_bounds__(256)
void gemm_kernel(const float* __restrict__ Ain,
                 const float* __restrict__ W,
                 const float* __restrict__ bias)
{
    const int tx = threadIdx.x;                 // 0..31
    const int ty = threadIdx.y;                 // 0..7
    const int j  = blockIdx.x * 128 + tx * 4;   // column
    const int i  = blockIdx.y * 8 + ty;         // row
    const int kz = blockIdx.z;
    const int k0 = kz * KH;

    float a0, a1, a2, a3;
    if (kz == 0) {
        const float4 bv = *reinterpret_cast<const float4*>(bias + j);
        a0 = bv.x; a1 = bv.y; a2 = bv.z; a3 = bv.w;
    } else {
        a0 = a1 = a2 = a3 = 0.f;
    }

    #pragma unroll 4
    for (int k = k0; k < k0 + KH; k += 4) {
        float4 av;
        if (SRCBUF == 0) {
            av = *reinterpret_cast<const float4*>(Ain + i * K + k);
        } else {
            const float* base = (SRCBUF == 1) ? g_h1p : g_h2p;
            av = *reinterpret_cast<const float4*>(base + i * K + k);
            #pragma unroll
            for (int p = 1; p < NPART; p++) {
                const float4 pv = *reinterpret_cast<const float4*>(
                    base + p * (BATCH * K) + i * K + k);
                av.x += pv.x; av.y += pv.y; av.z += pv.z; av.w += pv.w;
            }
            av.x = fmaxf(av.x, 0.f); av.y = fmaxf(av.y, 0.f);
            av.z = fmaxf(av.z, 0.f); av.w = fmaxf(av.w, 0.f);
        }
        const float aa[4] = {av.x, av.y, av.z, av.w};
        #pragma unroll
        for (int kk = 0; kk < 4; kk++) {
            const float4 wv = *reinterpret_cast<const float4*>(W + (k + kk) * N + j);
            a0 = fmaf(aa[kk], wv.x, a0);
            a1 = fmaf(aa[kk], wv.y, a1);
            a2 = fmaf(aa[kk], wv.z, a2);
            a3 = fmaf(aa[kk], wv.w, a3);
        }
    }

    if (DST == 0) {
        *reinterpret_cast<float4*>(g_h1p + kz * (BATCH * 512) + i * N + j) =
            make_float4(a0, a1, a2, a3);
    } else if (DST == 1) {
        *reinterpret_cast<float4*>(g_h2p + kz * (BATCH * 1024) + i * N + j) =
            make_float4(a0, a1, a2, a3);
    } else {
        // coeff[b][j], j in [0,512). j<256 -> "even" half, j>=256 -> "odd".
        const int side = (j >= 256) ? 1 : 0;
        const int jj   = j - side * 256;       // 4-aligned
        const int n    = jj >> 2;              // basis index; r = 0..3 across accs
        float* dst = g_om + kz * OMP_STRIDE + ((i * NB + n) * RANK) * 2 + side;
        dst[0] = a0; dst[2] = a1; dst[4] = a2; dst[6] = a3;
    }
}

// ---------------------------------------------------------------------------
// Basis + rank-4 projection. grid(SEQ/256, BATCH), block 256, 1 point/thread.
// Per (point, n): 1 ex2.approx + 1 cos.approx + 3 FMA-pipe ops + 8 FFMA
// accumulates (scalar — f32x2 is sm_103a-only). Sums KS3 omega partials
// in the prologue.
// ---------------------------------------------------------------------------
__global__ __launch_bounds__(256)
void basis_kernel(const float* __restrict__ t,
                  const float* __restrict__ mu,
                  const float* __restrict__ alpha,
                  const float* __restrict__ beta,
                  const float* __restrict__ gamma,
                  float* __restrict__ out)
{
    __shared__ __align__(16) float4 s_bp[NB];        // (a2, -a2*mu, beta, gamma)
    __shared__ __align__(16) float4 s_om[NB * 2];    // per n: {r0e,r0o,r1e,r1o},{r2e,r2o,r3e,r3o}

    const int tid = threadIdx.x;
    const int b   = blockIdx.y;

    if (tid < NB) {
        const float a2 = alpha[tid] * SQRT_LOG2E;
        s_bp[tid] = make_float4(a2, -a2 * mu[tid], beta[tid], gamma[tid]);
    }
    {
        // 512 floats of omega = 256 float2; sum KS3 partials
        const float2* src = reinterpret_cast<const float2*>(g_om + b * (NB * RANK * 2));
        float2 acc = src[tid];
        #pragma unroll
        for (int p = 1; p < KS3; p++) {
            const float2 pv = src[p * (OMP_STRIDE / 2) + tid];
            acc.x += pv.x; acc.y += pv.y;
        }
        reinterpret_cast<float2*>(s_om)[tid] = acc;
    }
    __syncthreads();

    const int s  = blockIdx.x * 256 + tid;
    const float tv = t[(size_t)b * SEQ + s];

    float ev0 = 0.f, ev1 = 0.f, ev2 = 0.f, ev3 = 0.f;
    float od0 = 0.f, od1 = 0.f, od2 = 0.f, od3 = 0.f;

    #pragma unroll 8
    for (int n = 0; n < NB; n++) {
        const float4 bp = s_bp[n];
        const float4 q0 = s_om[n * 2 + 0];
        const float4 q1 = s_om[n * 2 + 1];

        const float u  = fmaf(bp.x, tv, bp.y);      // sqrt(log2e)*alpha*(t - mu)
        const float nv = -u * u;
        float e;
        asm("ex2.approx.f32 %0, %1;" : "=f"(e) : "f"(nv));
        const float w = fmaf(bp.z, tv, bp.w);       // beta*t + gamma
        float c;
        asm("cos.approx.f32 %0, %1;" : "=f"(c) : "f"(w));
        const float pr = e * c;                     // h_t[b,s,n]

        ev0 = fmaf(pr, q0.x, ev0); od0 = fmaf(pr, q0.y, od0);
        ev1 = fmaf(pr, q0.z, ev1); od1 = fmaf(pr, q0.w, od1);
        ev2 = fmaf(pr, q1.x, ev2); od2 = fmaf(pr, q1.y, od2);
        ev3 = fmaf(pr, q1.z, ev3); od3 = fmaf(pr, q1.w, od3);
    }

    float4* op = reinterpret_cast<float4*>(
        out + (size_t)b * (2 * SEQ * RANK) + (size_t)s * 8);
    op[0] = make_float4(ev0, ev1, ev2, ev3);   // even row 2s
    op[1] = make_float4(od0, od1, od2, od3);   // odd  row 2s+1
}

// ---------------------------------------------------------------------------
// Launch
// ---------------------------------------------------------------------------
extern "C" void kernel_launch(void* const* d_in, const int* in_sizes, int n_in,
                              void* d_out, int out_size)
{
    const float* f     = (const float*)d_in[0];
    const float* t     = (const float*)d_in[1];
    const float* W1    = (const float*)d_in[2];
    const float* b1    = (const float*)d_in[3];
    const float* W2    = (const float*)d_in[4];
    const float* b2    = (const float*)d_in[5];
    const float* W3    = (const float*)d_in[6];
    const float* b3    = (const float*)d_in[7];
    const float* mu    = (const float*)d_in[8];
    const float* alpha = (const float*)d_in[9];
    const float* beta  = (const float*)d_in[10];
    const float* gamma = (const float*)d_in[11];
    float* out = (float*)d_out;

    const dim3 blk(32, 8);
    // h1 partials = f @ W1 (+b1 in split 0)                 [KS1][64, 512]
    gemm_kernel<128, 128 / KS1, 512, 0, 1, 0>
        <<<dim3(4, 8, KS1), blk>>>(f, W1, b1);
    // h2 partials = relu(sum h1p) @ W2 (+b2 in split 0)     [KS2][64, 1024]
    gemm_kernel<512, 512 / KS2, 1024, 1, KS1, 1>
        <<<dim3(8, 8, KS2), blk>>>(nullptr, W2, b2);
    // omega partials = relu(sum h2p) @ W3 (+b3)             [KS3][64, 512] packed
    gemm_kernel<1024, 1024 / KS3, 512, 2, KS2, 2>
        <<<dim3(4, 8, KS3), blk>>>(nullptr, W3, b3);
    // basis + projection
    basis_kernel<<<dim3(SEQ / 256, BATCH), 256>>>(t, mu, alpha, beta, gamma, out);
}

// round 4
// speedup vs baseline: 3.0627x; 1.3041x over previous
#include <cuda_runtime.h>
#include <cstdint>

#define BATCH 64
#define NB    64
#define RANK  4
#define SEQ   4096

// sqrt(log2(e)) — folds natural-exp into a single ex2.approx
#define SQRT_LOG2E 1.2011224087864498f

#define KS1 4    // split-K, layer 1
#define KS2 8    // split-K, layer 2
#define KS3 16   // split-K, layer 3
#define OMSZ (BATCH * NB * RANK * 2)   // floats per omega partial (32768)

// ---------------------------------------------------------------------------
// Scratch (device globals; no allocation allowed)
// ---------------------------------------------------------------------------
__device__ float g_h1p[KS1 * BATCH * 512];     // pre-relu partials of layer 1
__device__ float g_h2p[KS2 * BATCH * 1024];    // pre-relu partials of layer 2
__device__ float g_om [KS3 * OMSZ];            // packed omega partials
// omega packing within one partial: [((b*NB+n)*RANK+r)*2 + side]

// ---------------------------------------------------------------------------
// Tiled GEMM: block tile = all 64 batch rows x 64 cols; 256 threads as
// 16 tx (4 cols each) x 16 ty (4 rows each) -> 16 accumulators/thread.
// W and A staged through smem in 8-k chunks: W is read from L2 exactly once
// chip-wide; per-k compute is 2 broadcast LDS.128 + 16 FFMA per thread.
// Split-K via blockIdx.z -> disjoint partial buffers (bias only in split 0);
// the A-staging threads sum the producer's NPART partials (+relu) inline.
// SRC: 0 = Ain param (no relu), 1 = g_h1p, 2 = g_h2p
// DST: 0 = g_h1p partial, 1 = g_h2p partial, 2 = packed omega partial
// ---------------------------------------------------------------------------
template <int K, int N, int KS, int SRC, int NPART, int DST>
__global__ __launch_bounds__(256)
void gemm_tiled(const float* __restrict__ Ain,
                const float* __restrict__ W,
                const float* __restrict__ bias)
{
    __shared__ __align__(16) float sW[8][64];   // [kk][col]
    __shared__ __align__(16) float sA[8][64];   // [kk][b] (transposed)

    const int tid = threadIdx.x;
    const int tx  = tid & 15;          // col quad
    const int ty  = tid >> 4;          // row quad
    const int j0  = blockIdx.x * 64;
    const int z   = blockIdx.z;
    constexpr int KC = K / KS;
    const int k0  = z * KC;

    float acc[4][4];
    #pragma unroll
    for (int r = 0; r < 4; r++) {
        #pragma unroll
        for (int c = 0; c < 4; c++) acc[r][c] = 0.f;
    }

    for (int kc = 0; kc < KC; kc += 8) {
        // ---- stage ----
        if (tid < 128) {
            const int kk = tid >> 4, c4 = (tid & 15) * 4;
            *reinterpret_cast<float4*>(&sW[kk][c4]) =
                *reinterpret_cast<const float4*>(W + (size_t)(k0 + kc + kk) * N + j0 + c4);
        } else {
            const int i  = tid - 128;          // 0..127
            const int b  = i >> 1;             // 0..63
            const int kq = (i & 1) * 4;        // which 4 of the 8 k's
            float4 av;
            if (SRC == 0) {
                av = *reinterpret_cast<const float4*>(Ain + b * K + k0 + kc + kq);
            } else {
                const float* base = (SRC == 1) ? g_h1p : g_h2p;
                const float* p0 = base + b * K + k0 + kc + kq;
                av = *reinterpret_cast<const float4*>(p0);
                #pragma unroll
                for (int p = 1; p < NPART; p++) {
                    const float4 pv = *reinterpret_cast<const float4*>(p0 + p * (BATCH * K));
                    av.x += pv.x; av.y += pv.y; av.z += pv.z; av.w += pv.w;
                }
                av.x = fmaxf(av.x, 0.f); av.y = fmaxf(av.y, 0.f);
                av.z = fmaxf(av.z, 0.f); av.w = fmaxf(av.w, 0.f);
            }
            sA[kq + 0][b] = av.x; sA[kq + 1][b] = av.y;
            sA[kq + 2][b] = av.z; sA[kq + 3][b] = av.w;
        }
        __syncthreads();

        // ---- compute ----
        #pragma unroll
        for (int kk = 0; kk < 8; kk++) {
            const float4 wv = *reinterpret_cast<const float4*>(&sW[kk][tx * 4]);
            const float4 av = *reinterpret_cast<const float4*>(&sA[kk][ty * 4]);
            const float aa[4] = {av.x, av.y, av.z, av.w};
            const float ww[4] = {wv.x, wv.y, wv.z, wv.w};
            #pragma unroll
            for (int r = 0; r < 4; r++) {
                #pragma unroll
                for (int c = 0; c < 4; c++)
                    acc[r][c] = fmaf(aa[r], ww[c], acc[r][c]);
            }
        }
        __syncthreads();
    }

    // ---- epilogue ----
    const int j = j0 + tx * 4;
    if (z == 0) {
        const float4 bv = *reinterpret_cast<const float4*>(bias + j);
        #pragma unroll
        for (int r = 0; r < 4; r++) {
            acc[r][0] += bv.x; acc[r][1] += bv.y;
            acc[r][2] += bv.z; acc[r][3] += bv.w;
        }
    }
    #pragma unroll
    for (int r = 0; r < 4; r++) {
        const int b = ty * 4 + r;
        if (DST == 0) {
            *reinterpret_cast<float4*>(g_h1p + z * (BATCH * 512) + b * 512 + j) =
                make_float4(acc[r][0], acc[r][1], acc[r][2], acc[r][3]);
        } else if (DST == 1) {
            *reinterpret_cast<float4*>(g_h2p + z * (BATCH * 1024) + b * 1024 + j) =
                make_float4(acc[r][0], acc[r][1], acc[r][2], acc[r][3]);
        } else {
            // coeff col j in [0,512): j<256 -> "even" half, j>=256 -> "odd".
            const int side = (j >= 256) ? 1 : 0;
            const int n    = (j - side * 256) >> 2;   // basis index; c = rank
            float* dst = g_om + z * OMSZ + ((b * NB + n) * RANK) * 2 + side;
            dst[0] = acc[r][0]; dst[2] = acc[r][1];
            dst[4] = acc[r][2]; dst[6] = acc[r][3];
        }
    }
}

// ---------------------------------------------------------------------------
// Basis + rank-4 projection. grid(SEQ/512, BATCH), block 256, 2 points/thread
// (amortizes the 3 LDS.128/n over 2 points). Per (point, n): ex2.approx +
// cos.approx + 4 fma-pipe ops + 8 scalar FFMA. Sums KS3 omega partials in
// the prologue.
// ---------------------------------------------------------------------------
__global__ __launch_bounds__(256)
void basis_kernel(const float* __restrict__ t,
                  const float* __restrict__ mu,
                  const float* __restrict__ alpha,
                  const float* __restrict__ beta,
                  const float* __restrict__ gamma,
                  float* __restrict__ out)
{
    __shared__ __align__(16) float4 s_bp[NB];        // (a2, -a2*mu, beta, gamma)
    __shared__ __align__(16) float4 s_om[NB * 2];    // per n: {r0e,r0o,r1e,r1o},{r2e,r2o,r3e,r3o}

    const int tid = threadIdx.x;
    const int b   = blockIdx.y;

    if (tid < NB) {
        const float a2 = alpha[tid] * SQRT_LOG2E;
        s_bp[tid] = make_float4(a2, -a2 * mu[tid], beta[tid], gamma[tid]);
    }
    {
        const float2* src = reinterpret_cast<const float2*>(g_om + b * (NB * RANK * 2));
        float2 acc = src[tid];
        #pragma unroll
        for (int p = 1; p < KS3; p++) {
            const float2 pv = src[p * (OMSZ / 2) + tid];
            acc.x += pv.x; acc.y += pv.y;
        }
        reinterpret_cast<float2*>(s_om)[tid] = acc;
    }
    __syncthreads();

    const int s0 = blockIdx.x * 512 + tid;
    const float* trow = t + (size_t)b * SEQ;
    const float tv0 = trow[s0];
    const float tv1 = trow[s0 + 256];

    float ev[2][4], od[2][4];
    #pragma unroll
    for (int p = 0; p < 2; p++) {
        #pragma unroll
        for (int r = 0; r < 4; r++) { ev[p][r] = 0.f; od[p][r] = 0.f; }
    }

    #pragma unroll 4
    for (int n = 0; n < NB; n++) {
        const float4 bp = s_bp[n];
        const float4 q0 = s_om[n * 2 + 0];
        const float4 q1 = s_om[n * 2 + 1];
        const float tvs[2] = {tv0, tv1};

        #pragma unroll
        for (int p = 0; p < 2; p++) {
            const float u  = fmaf(bp.x, tvs[p], bp.y);   // sqrt(log2e)*alpha*(t-mu)
            const float nv = -u * u;
            float e;
            asm("ex2.approx.f32 %0, %1;" : "=f"(e) : "f"(nv));
            const float w = fmaf(bp.z, tvs[p], bp.w);    // beta*t + gamma
            float c;
            asm("cos.approx.f32 %0, %1;" : "=f"(c) : "f"(w));
            const float pr = e * c;                      // h_t[b,s,n]

            ev[p][0] = fmaf(pr, q0.x, ev[p][0]); od[p][0] = fmaf(pr, q0.y, od[p][0]);
            ev[p][1] = fmaf(pr, q0.z, ev[p][1]); od[p][1] = fmaf(pr, q0.w, od[p][1]);
            ev[p][2] = fmaf(pr, q1.x, ev[p][2]); od[p][2] = fmaf(pr, q1.y, od[p][2]);
            ev[p][3] = fmaf(pr, q1.z, ev[p][3]); od[p][3] = fmaf(pr, q1.w, od[p][3]);
        }
    }

    float* obase = out + (size_t)b * (2 * SEQ * RANK);
    #pragma unroll
    for (int p = 0; p < 2; p++) {
        const int s = s0 + 256 * p;
        float4* op = reinterpret_cast<float4*>(obase + (size_t)s * 8);
        op[0] = make_float4(ev[p][0], ev[p][1], ev[p][2], ev[p][3]);   // row 2s
        op[1] = make_float4(od[p][0], od[p][1], od[p][2], od[p][3]);   // row 2s+1
    }
}

// ---------------------------------------------------------------------------
// Launch
// ---------------------------------------------------------------------------
extern "C" void kernel_launch(void* const* d_in, const int* in_sizes, int n_in,
                              void* d_out, int out_size)
{
    const float* f     = (const float*)d_in[0];
    const float* t     = (const float*)d_in[1];
    const float* W1    = (const float*)d_in[2];
    const float* b1    = (const float*)d_in[3];
    const float* W2    = (const float*)d_in[4];
    const float* b2    = (const float*)d_in[5];
    const float* W3    = (const float*)d_in[6];
    const float* b3    = (const float*)d_in[7];
    const float* mu    = (const float*)d_in[8];
    const float* alpha = (const float*)d_in[9];
    const float* beta  = (const float*)d_in[10];
    const float* gamma = (const float*)d_in[11];
    float* out = (float*)d_out;

    // h1 partials = f @ W1 (+b1 in split 0)               [KS1][64, 512]
    gemm_tiled<128, 512, KS1, 0, 1, 0>
        <<<dim3(8, 1, KS1), 256>>>(f, W1, b1);
    // h2 partials = relu(sum h1p) @ W2 (+b2 in split 0)   [KS2][64, 1024]
    gemm_tiled<512, 1024, KS2, 1, KS1, 1>
        <<<dim3(16, 1, KS2), 256>>>(nullptr, W2, b2);
    // omega partials = relu(sum h2p) @ W3 (+b3)           [KS3][64, 512] packed
    gemm_tiled<1024, 512, KS3, 2, KS2, 2>
        <<<dim3(8, 1, KS3), 256>>>(nullptr, W3, b3);
    // basis + projection
    basis_kernel<<<dim3(SEQ / 512, BATCH), 256>>>(t, mu, alpha, beta, gamma, out);
}

// round 5
// speedup vs baseline: 3.1825x; 1.0391x over previous
#include <cuda_runtime.h>
#include <cstdint>

#define BATCH 64
#define NB    64
#define RANK  4
#define SEQ   4096

// sqrt(log2(e)) — folds natural-exp into a single ex2.approx
#define SQRT_LOG2E 1.2011224087864498f

#define KS1 4    // split-K, layer 1
#define KS2 8    // split-K, layer 2
#define KS3 16   // split-K, layer 3
#define OMSZ (BATCH * NB * RANK * 2)   // floats per omega partial (32768)

// ---------------------------------------------------------------------------
// Scratch (device globals; no allocation allowed)
// ---------------------------------------------------------------------------
__device__ float g_h1p[KS1 * BATCH * 512];     // pre-relu partials of layer 1
__device__ float g_h2p[KS2 * BATCH * 1024];    // pre-relu partials of layer 2
__device__ float g_om [KS3 * OMSZ];            // packed omega partials
// omega packing within one partial: [((b*NB+n)*RANK+r)*2 + side]

// ---------------------------------------------------------------------------
// Tiled GEMM: block tile = 64 batch rows x 64 cols; 256 threads as 16 tx
// (4 cols) x 16 ty (4 rows); accumulators held as 8 packed f32x2 (col pairs).
// Double-buffered smem staging: chunk c+1 is prefetched into registers while
// chunk c is computed (one barrier per chunk). W is read from L2 once
// chip-wide. Split-K via blockIdx.z -> disjoint partial buffers (bias only
// in split 0); A-staging threads sum the producer's NPART partials (+relu).
// SRC: 0 = Ain param (no relu), 1 = g_h1p, 2 = g_h2p
// DST: 0 = g_h1p partial, 1 = g_h2p partial, 2 = packed omega partial
// ---------------------------------------------------------------------------
template <int K, int N, int KS, int SRC, int NPART, int DST>
__global__ __launch_bounds__(256)
void gemm_tiled(const float* __restrict__ Ain,
                const float* __restrict__ W,
                const float* __restrict__ bias)
{
    constexpr int KC  = K / KS;     // k-range per block
    constexpr int NCH = KC / 8;     // 8-k chunks

    __shared__ __align__(16) float sW[2][8][64];   // [buf][kk][col]
    __shared__ __align__(16) float sA[2][8][64];   // [buf][kk][b]

    const int tid = threadIdx.x;
    const int tx  = tid & 15;          // col quad
    const int ty  = tid >> 4;          // row quad
    const int j0  = blockIdx.x * 64;
    const int z   = blockIdx.z;
    const int k0  = z * KC;

    const bool isW = tid < 128;
    const int w_kk = tid >> 4;             // valid if isW
    const int w_c4 = (tid & 15) * 4;
    const int a_i  = tid - 128;
    const int a_b  = a_i >> 1;
    const int a_kq = (a_i & 1) * 4;

    auto load_chunk = [&](int kc) -> float4 {
        if (isW) {
            return *reinterpret_cast<const float4*>(
                W + (size_t)(k0 + kc + w_kk) * N + j0 + w_c4);
        }
        float4 av;
        if (SRC == 0) {
            av = *reinterpret_cast<const float4*>(Ain + a_b * K + k0 + kc + a_kq);
        } else {
            const float* base = (SRC == 1) ? g_h1p : g_h2p;
            const float* p0 = base + a_b * K + k0 + kc + a_kq;
            av = *reinterpret_cast<const float4*>(p0);
            #pragma unroll
            for (int p = 1; p < NPART; p++) {
                const float4 pv = *reinterpret_cast<const float4*>(p0 + p * (BATCH * K));
                av.x += pv.x; av.y += pv.y; av.z += pv.z; av.w += pv.w;
            }
            av.x = fmaxf(av.x, 0.f); av.y = fmaxf(av.y, 0.f);
            av.z = fmaxf(av.z, 0.f); av.w = fmaxf(av.w, 0.f);
        }
        return av;
    };
    auto store_chunk = [&](int buf, float4 v) {
        if (isW) {
            *reinterpret_cast<float4*>(&sW[buf][w_kk][w_c4]) = v;
        } else {
            sA[buf][a_kq + 0][a_b] = v.x;
            sA[buf][a_kq + 1][a_b] = v.y;
            sA[buf][a_kq + 2][a_b] = v.z;
            sA[buf][a_kq + 3][a_b] = v.w;
        }
    };

    unsigned long long acc2[4][2];   // [row r][col pair]
    #pragma unroll
    for (int r = 0; r < 4; r++) { acc2[r][0] = 0ull; acc2[r][1] = 0ull; }

    float4 st = load_chunk(0);
    store_chunk(0, st);
    __syncthreads();

    for (int c = 0; c < NCH; c++) {
        float4 nx;
        if (c + 1 < NCH) nx = load_chunk((c + 1) * 8);

        const int buf = c & 1;
        #pragma unroll
        for (int kk = 0; kk < 8; kk++) {
            const ulonglong2 wq =
                *reinterpret_cast<const ulonglong2*>(&sW[buf][kk][tx * 4]);
            const float4 av = *reinterpret_cast<const float4*>(&sA[buf][kk][ty * 4]);
            const float aa[4] = {av.x, av.y, av.z, av.w};
            #pragma unroll
            for (int r = 0; r < 4; r++) {
                unsigned long long ap;
                asm("mov.b64 %0, {%1, %1};" : "=l"(ap) : "f"(aa[r]));
                asm("fma.rn.f32x2 %0, %1, %2, %0;"
                    : "+l"(acc2[r][0]) : "l"(ap), "l"(wq.x));
                asm("fma.rn.f32x2 %0, %1, %2, %0;"
                    : "+l"(acc2[r][1]) : "l"(ap), "l"(wq.y));
            }
        }

        if (c + 1 < NCH) store_chunk((c + 1) & 1, nx);
        __syncthreads();
    }

    // ---- epilogue ----
    float o[4][4];
    #pragma unroll
    for (int r = 0; r < 4; r++) {
        asm("mov.b64 {%0, %1}, %2;" : "=f"(o[r][0]), "=f"(o[r][1]) : "l"(acc2[r][0]));
        asm("mov.b64 {%0, %1}, %2;" : "=f"(o[r][2]), "=f"(o[r][3]) : "l"(acc2[r][1]));
    }
    const int j = j0 + tx * 4;
    if (z == 0) {
        const float4 bv = *reinterpret_cast<const float4*>(bias + j);
        #pragma unroll
        for (int r = 0; r < 4; r++) {
            o[r][0] += bv.x; o[r][1] += bv.y; o[r][2] += bv.z; o[r][3] += bv.w;
        }
    }
    #pragma unroll
    for (int r = 0; r < 4; r++) {
        const int b = ty * 4 + r;
        if (DST == 0) {
            *reinterpret_cast<float4*>(g_h1p + z * (BATCH * 512) + b * 512 + j) =
                make_float4(o[r][0], o[r][1], o[r][2], o[r][3]);
        } else if (DST == 1) {
            *reinterpret_cast<float4*>(g_h2p + z * (BATCH * 1024) + b * 1024 + j) =
                make_float4(o[r][0], o[r][1], o[r][2], o[r][3]);
        } else {
            const int side = (j >= 256) ? 1 : 0;
            const int n    = (j - side * 256) >> 2;   // basis index; cols = ranks
            float* dst = g_om + z * OMSZ + ((b * NB + n) * RANK) * 2 + side;
            dst[0] = o[r][0]; dst[2] = o[r][1];
            dst[4] = o[r][2]; dst[6] = o[r][3];
        }
    }
}

// ---------------------------------------------------------------------------
// Basis + rank-4 projection. grid(SEQ/256, BATCH) = 1024 blocks of 128
// threads, 2 points/thread. Per (point, n): ex2.approx + cos.approx +
// 4 scalar fma-pipe ops + 1 pack mov + 4 packed fma.rn.f32x2 (even,odd per
// rank). Sums KS3 omega partials in the prologue.
// ---------------------------------------------------------------------------
__global__ __launch_bounds__(128)
void basis_kernel(const float* __restrict__ t,
                  const float* __restrict__ mu,
                  const float* __restrict__ alpha,
                  const float* __restrict__ beta,
                  const float* __restrict__ gamma,
                  float* __restrict__ out)
{
    __shared__ __align__(16) float4 s_bp[NB];        // (a2, -a2*mu, beta, gamma)
    __shared__ __align__(16) float2 s_om[NB * RANK]; // (even, odd) per (n, r)

    const int tid = threadIdx.x;
    const int b   = blockIdx.y;

    if (tid < NB) {
        const float a2 = alpha[tid] * SQRT_LOG2E;
        s_bp[tid] = make_float4(a2, -a2 * mu[tid], beta[tid], gamma[tid]);
    }
    {
        const float2* src = reinterpret_cast<const float2*>(g_om + b * (NB * RANK * 2));
        #pragma unroll
        for (int e = tid; e < NB * RANK; e += 128) {
            float2 acc = src[e];
            #pragma unroll
            for (int p = 1; p < KS3; p++) {
                const float2 pv = src[p * (OMSZ / 2) + e];
                acc.x += pv.x; acc.y += pv.y;
            }
            s_om[e] = acc;
        }
    }
    __syncthreads();

    const int s0 = blockIdx.x * 256 + tid;
    const float* trow = t + (size_t)b * SEQ;
    const float tvs[2] = {trow[s0], trow[s0 + 128]};

    unsigned long long acc[RANK][2];
    #pragma unroll
    for (int r = 0; r < RANK; r++) { acc[r][0] = 0ull; acc[r][1] = 0ull; }

    const unsigned long long* omq =
        reinterpret_cast<const unsigned long long*>(s_om);

    #pragma unroll 4
    for (int n = 0; n < NB; n++) {
        const float4 bp = s_bp[n];
        const ulonglong2 q0 = *reinterpret_cast<const ulonglong2*>(omq + n * 4);
        const ulonglong2 q1 = *reinterpret_cast<const ulonglong2*>(omq + n * 4 + 2);
        const unsigned long long O[4] = {q0.x, q0.y, q1.x, q1.y};

        #pragma unroll
        for (int p = 0; p < 2; p++) {
            const float u  = fmaf(bp.x, tvs[p], bp.y);   // sqrt(log2e)*alpha*(t-mu)
            const float nv = -u * u;
            float e;
            asm("ex2.approx.f32 %0, %1;" : "=f"(e) : "f"(nv));
            const float w = fmaf(bp.z, tvs[p], bp.w);    // beta*t + gamma
            float c;
            asm("cos.approx.f32 %0, %1;" : "=f"(c) : "f"(w));
            const float pr = e * c;                      // h_t[b,s,n]
            unsigned long long pp;
            asm("mov.b64 %0, {%1, %1};" : "=l"(pp) : "f"(pr));
            #pragma unroll
            for (int r = 0; r < RANK; r++)
                asm("fma.rn.f32x2 %0, %1, %2, %0;"
                    : "+l"(acc[r][p]) : "l"(pp), "l"(O[r]));
        }
    }

    float* obase = out + (size_t)b * (2 * SEQ * RANK);
    #pragma unroll
    for (int p = 0; p < 2; p++) {
        const int s = s0 + 128 * p;
        float ev[4], od[4];
        #pragma unroll
        for (int r = 0; r < RANK; r++)
            asm("mov.b64 {%0, %1}, %2;" : "=f"(ev[r]), "=f"(od[r]) : "l"(acc[r][p]));
        float4* op = reinterpret_cast<float4*>(obase + (size_t)s * 8);
        op[0] = make_float4(ev[0], ev[1], ev[2], ev[3]);   // row 2s
        op[1] = make_float4(od[0], od[1], od[2], od[3]);   // row 2s+1
    }
}

// ---------------------------------------------------------------------------
// Launch
// ---------------------------------------------------------------------------
extern "C" void kernel_launch(void* const* d_in, const int* in_sizes, int n_in,
                              void* d_out, int out_size)
{
    const float* f     = (const float*)d_in[0];
    const float* t     = (const float*)d_in[1];
    const float* W1    = (const float*)d_in[2];
    const float* b1    = (const float*)d_in[3];
    const float* W2    = (const float*)d_in[4];
    const float* b2    = (const float*)d_in[5];
    const float* W3    = (const float*)d_in[6];
    const float* b3    = (const float*)d_in[7];
    const float* mu    = (const float*)d_in[8];
    const float* alpha = (const float*)d_in[9];
    const float* beta  = (const float*)d_in[10];
    const float* gamma = (const float*)d_in[11];
    float* out = (float*)d_out;

    // h1 partials = f @ W1 (+b1 in split 0)               [KS1][64, 512]
    gemm_tiled<128, 512, KS1, 0, 1, 0>
        <<<dim3(8, 1, KS1), 256>>>(f, W1, b1);
    // h2 partials = relu(sum h1p) @ W2 (+b2 in split 0)   [KS2][64, 1024]
    gemm_tiled<512, 1024, KS2, 1, KS1, 1>
        <<<dim3(16, 1, KS2), 256>>>(nullptr, W2, b2);
    // omega partials = relu(sum h2p) @ W3 (+b3)           [KS3][64, 512] packed
    gemm_tiled<1024, 512, KS3, 2, KS2, 2>
        <<<dim3(8, 1, KS3), 256>>>(nullptr, W3, b3);
    // basis + projection
    basis_kernel<<<dim3(SEQ / 256, BATCH), 128>>>(t, mu, alpha, beta, gamma, out);
}